// round 12
// baseline (speedup 1.0000x reference)
#include <cuda_runtime.h>
#include <cstdlib>

#define NUM_SEG      32
#define MUL          128
#define D            3
#define NUM_PATHS    64
#define SEG_ELEMS    (MUL * D)              // 384 floats per segment
#define ROW_ELEMS    (NUM_SEG * SEG_ELEMS)  // 12288 floats per batch row
#define ROWS_PER_CTA 2                      // 2 rows x 2 half-row warps per CTA

// Schedule in rank-sorted (by idx2) order; built once per launch by ftp3_setup.
__device__ int g_off0[NUM_PATHS];      // rank -> idx0[p]*SEG_ELEMS
__device__ int g_out[NUM_PATHS];       // rank -> seg*SEG_ELEMS at boundary, else -1
__device__ int g_coefoff[NUM_PATHS];   // rank -> p*27
__device__ int g_x1off[NUM_PATHS];     // rank -> idx1[p]*3
__device__ int g_emptyoff[NUM_SEG];    // seg -> seg*SEG_ELEMS if empty, else -1
__device__ int g_split;                // segment-aligned split nearest rank 32

__global__ void ftp3_setup(const int* __restrict__ idx0,
                           const int* __restrict__ idx1,
                           const int* __restrict__ idx2)
{
    __shared__ int sk[NUM_PATHS];
    __shared__ int skey[NUM_PATHS];
    const int t = threadIdx.x;            // 64 threads
    sk[t] = idx2[t];
    __syncthreads();

    const int key = sk[t];
    int r = 0, nlater = 0;
    #pragma unroll
    for (int q = 0; q < NUM_PATHS; ++q) {
        const int kq = sk[q];
        r      += (kq < key) | ((kq == key) & (q < t));
        nlater += (kq == key) & (q > t);
    }
    skey[r]      = key;
    g_off0[r]    = idx0[t] * SEG_ELEMS;
    g_out[r]     = (nlater == 0) ? key * SEG_ELEMS : -1;
    g_coefoff[r] = t * 27;
    g_x1off[r]   = idx1[t] * D;
    if (t < NUM_SEG) {
        int c = 0;
        #pragma unroll
        for (int q = 0; q < NUM_PATHS; ++q) c += (sk[q] == t);
        g_emptyoff[t] = (c == 0) ? t * SEG_ELEMS : -1;
    }
    __syncthreads();
    if (t == 0) {
        int best = 0;
        for (int r2 = 1; r2 <= NUM_PATHS; ++r2) {
            const bool bnd = (r2 == NUM_PATHS) || (skey[r2] != skey[r2 - 1]);
            if (bnd && abs(r2 - 32) < abs(best - 32)) best = r2;
        }
        g_split = best;
    }
}

__global__ __launch_bounds__(128, 5)     // ~100 regs: full per-warp MLP (per R9 build)
void ftp3_main(const float* __restrict__ x0,
               const float* __restrict__ x1,
               const float* __restrict__ coeff,
               float*       __restrict__ out)
{
    __shared__ __align__(16) float M[ROWS_PER_CTA][NUM_PATHS * 12];
    __shared__ int s_off0[NUM_PATHS];
    __shared__ int s_out[NUM_PATHS];
    __shared__ int s_empty[NUM_SEG];
    __shared__ int s_split;

    const int t    = threadIdx.x;
    const int w    = t >> 5;
    const int lane = t & 31;
    const int row  = w >> 1;              // 0..1
    const int half = w & 1;               // 0..1
    const int b0   = blockIdx.x * ROWS_PER_CTA;

    // Cheap prologue: copy schedule, build M (one job per thread), one sync.
    if (t < NUM_PATHS) {
        s_off0[t] = g_off0[t];
        s_out[t]  = g_out[t];
    } else if (t < NUM_PATHS + NUM_SEG) {
        s_empty[t - NUM_PATHS] = g_emptyoff[t - NUM_PATHS];
    } else if (t == NUM_PATHS + NUM_SEG) {
        s_split = g_split;
    }
    {
        const int rw = t >> 6;            // row for this M job
        const int r  = t & (NUM_PATHS - 1);
        const float* c   = coeff + g_coefoff[r];                 // [i][j][k]
        const float* x1b = x1 + (size_t)(b0 + rw) * (NUM_SEG * D) + g_x1off[r];
        const float j0 = x1b[0], j1 = x1b[1], j2 = x1b[2];
        float* Mr = &M[rw][r * 12];
        #pragma unroll
        for (int i = 0; i < 3; ++i)
            #pragma unroll
            for (int k = 0; k < 3; ++k)
                Mr[i * 3 + k] =
                    j0 * c[i * 9 + 0 * 3 + k] +
                    j1 * c[i * 9 + 1 * 3 + k] +
                    j2 * c[i * 9 + 2 * 3 + k];
        Mr[9] = 0.f; Mr[10] = 0.f; Mr[11] = 0.f;
    }
    __syncthreads();

    // Main loop: warp (row, half); lane owns u = 4*lane..4*lane+3 ->
    // 3 aligned float4 per segment; every LDG/STG is a full 512B warp txn.
    const float*  x0b  = x0  + (size_t)(b0 + row) * ROW_ELEMS;
    float*        outb = out + (size_t)(b0 + row) * ROW_ELEMS;
    const float4* M4   = (const float4*)M[row];
    const int     t3   = lane * 3;

    const int qs = half ? s_split : 0;
    const int qe = half ? NUM_PATHS : s_split;

    float acc[12];
    #pragma unroll
    for (int i = 0; i < 12; ++i) acc[i] = 0.f;

    #pragma unroll 4
    for (int q = qs; q < qe; ++q) {
        const float4* xs = (const float4*)(x0b + s_off0[q]) + t3;
        const float4 v0 = xs[0];
        const float4 v1 = xs[1];
        const float4 v2 = xs[2];
        const float a[12] = { v0.x, v0.y, v0.z, v0.w,
                              v1.x, v1.y, v1.z, v1.w,
                              v2.x, v2.y, v2.z, v2.w };

        const float4 q0 = M4[q * 3 + 0];
        const float4 q1 = M4[q * 3 + 1];
        const float4 q2 = M4[q * 3 + 2];
        const float m[9] = { q0.x, q0.y, q0.z, q0.w,
                             q1.x, q1.y, q1.z, q1.w, q2.x };

        #pragma unroll
        for (int u = 0; u < 4; ++u)
            #pragma unroll
            for (int k = 0; k < 3; ++k)
                acc[u * 3 + k] += a[u * 3 + 0] * m[0 + k]
                                + a[u * 3 + 1] * m[3 + k]
                                + a[u * 3 + 2] * m[6 + k];

        const int oo = s_out[q];          // warp-uniform branch
        if (oo >= 0) {
            float4* o = (float4*)(outb + oo) + t3;
            o[0] = make_float4(acc[0], acc[1], acc[2],  acc[3]);
            o[1] = make_float4(acc[4], acc[5], acc[6],  acc[7]);
            o[2] = make_float4(acc[8], acc[9], acc[10], acc[11]);
            #pragma unroll
            for (int i = 0; i < 12; ++i) acc[i] = 0.f;
        }
    }

    // Zero-fill empty segments (poisoned output); split by segment parity.
    const float4 z = make_float4(0.f, 0.f, 0.f, 0.f);
    #pragma unroll
    for (int s = 0; s < NUM_SEG; ++s) {
        const int eo = s_empty[s];
        if (eo >= 0 && (s & 1) == half) {
            float4* o = (float4*)(outb + eo) + t3;
            o[0] = z; o[1] = z; o[2] = z;
        }
    }
}

extern "C" void kernel_launch(void* const* d_in, const int* in_sizes, int n_in,
                              void* d_out, int out_size)
{
    const float* x0    = (const float*)d_in[0];  // (2048, 12288)
    const float* x1    = (const float*)d_in[1];  // (2048, 96)
    const float* coeff = (const float*)d_in[2];  // (64, 27)
    const int*   idx0  = (const int*)d_in[3];
    const int*   idx1  = (const int*)d_in[4];
    const int*   idx2  = (const int*)d_in[5];
    float*       out   = (float*)d_out;          // (2048, 12288)

    const int batch = in_sizes[0] / ROW_ELEMS;   // 2048

    ftp3_setup<<<1, 64>>>(idx0, idx1, idx2);
    ftp3_main<<<batch / ROWS_PER_CTA, 128>>>(x0, x1, coeff, out);
}

// round 13
// speedup vs baseline: 1.1927x; 1.1927x over previous
#include <cuda_runtime.h>
#include <cstdlib>

#define NUM_SEG      32
#define MUL          128
#define D            3
#define NUM_PATHS    64
#define SEG_ELEMS    (MUL * D)              // 384 floats per segment
#define ROW_ELEMS    (NUM_SEG * SEG_ELEMS)  // 12288 floats per batch row
#define ROWS_PER_CTA 2                      // 2 rows x 2 half-row warps per CTA

__global__ __launch_bounds__(128, 5)        // ~100 regs: full per-warp MLP
void ftp3_main(const float* __restrict__ x0,
               const float* __restrict__ x1,
               const float* __restrict__ coeff,
               const int*   __restrict__ idx0,
               const int*   __restrict__ idx1,
               const int*   __restrict__ idx2,
               float*       __restrict__ out)
{
    __shared__ __align__(16) float M[ROWS_PER_CTA][NUM_PATHS * 12];
    __shared__ int s_idx2[NUM_PATHS];
    __shared__ int s_key[NUM_PATHS];      // rank -> segment key (sorted)
    __shared__ int s_porder[NUM_PATHS];   // rank -> original path id
    __shared__ int s_off0[NUM_PATHS];     // rank -> idx0[p]*SEG_ELEMS
    __shared__ int s_out[NUM_PATHS];      // rank -> seg*SEG_ELEMS at boundary, else -1
    __shared__ int s_empty[NUM_SEG];      // seg offset to zero-fill, or -1
    __shared__ int s_best;                // packed best split: (|r-32|<<8)|r

    const int t    = threadIdx.x;
    const int w    = t >> 5;
    const int lane = t & 31;
    const int row  = w >> 1;              // 0..1 : row within CTA
    const int half = w & 1;               // 0..1 : path-range of that row
    const int b0   = blockIdx.x * ROWS_PER_CTA;

    if (t < NUM_PATHS) s_idx2[t] = idx2[t];
    if (t == NUM_PATHS) s_best = 0x7fffffff;
    __syncthreads();

    // Stage 1: stable counting-rank of paths by idx2 (partial unroll: cheap
    // latency without the full-unroll register blowup), plus empty-seg scan.
    if (t < NUM_PATHS) {
        const int key = s_idx2[t];
        int r = 0, nlater = 0;
        #pragma unroll 4
        for (int q = 0; q < NUM_PATHS; ++q) {
            const int kq = s_idx2[q];
            r      += (kq < key) | ((kq == key) & (q < t));
            nlater += (kq == key) & (q > t);
        }
        s_key[r]    = key;
        s_porder[r] = t;
        s_off0[r]   = idx0[t] * SEG_ELEMS;
        s_out[r]    = (nlater == 0) ? key * SEG_ELEMS : -1;
    } else if (t < NUM_PATHS + NUM_SEG) {
        const int s = t - NUM_PATHS;
        int c = 0;
        #pragma unroll 4
        for (int q = 0; q < NUM_PATHS; ++q) c += (s_idx2[q] == s);
        s_empty[s] = (c == 0) ? s * SEG_ELEMS : -1;
    }
    __syncthreads();

    // Stage 2a: parallel split search — boundary rank nearest 32.
    if (t >= 1 && t <= NUM_PATHS) {
        const bool bnd = (t == NUM_PATHS) || (s_key[t] != s_key[t - 1]);
        if (bnd) atomicMin(&s_best, (abs(t - 32) << 8) | t);
    }
    // Stage 2b: build M, one (row, rank) job per thread.
    {
        const int rw = t >> 6;            // row for this job
        const int r  = t & (NUM_PATHS - 1);
        const int p  = s_porder[r];
        const float* c   = coeff + p * 27;                       // [i][j][k]
        const float* x1b = x1 + (size_t)(b0 + rw) * (NUM_SEG * D) + idx1[p] * D;
        const float j0 = x1b[0], j1 = x1b[1], j2 = x1b[2];
        float* Mr = &M[rw][r * 12];
        #pragma unroll
        for (int i = 0; i < 3; ++i)
            #pragma unroll
            for (int k = 0; k < 3; ++k)
                Mr[i * 3 + k] =
                    j0 * c[i * 9 + 0 * 3 + k] +
                    j1 * c[i * 9 + 1 * 3 + k] +
                    j2 * c[i * 9 + 2 * 3 + k];
        Mr[9] = 0.f; Mr[10] = 0.f; Mr[11] = 0.f;
    }
    __syncthreads();

    // Main loop (R10 structure, unchanged): warp (row, half); lane owns
    // u = 4*lane..4*lane+3 -> 3 aligned float4 per segment; every LDG/STG
    // is a fully-coalesced 512B warp transaction.
    const float*  x0b  = x0  + (size_t)(b0 + row) * ROW_ELEMS;
    float*        outb = out + (size_t)(b0 + row) * ROW_ELEMS;
    const float4* M4   = (const float4*)M[row];
    const int     t3   = lane * 3;
    const int     split = s_best & 0xff;

    const int qs = half ? split : 0;
    const int qe = half ? NUM_PATHS : split;

    float acc[12];
    #pragma unroll
    for (int i = 0; i < 12; ++i) acc[i] = 0.f;

    #pragma unroll 4
    for (int q = qs; q < qe; ++q) {
        const float4* xs = (const float4*)(x0b + s_off0[q]) + t3;
        const float4 v0 = xs[0];
        const float4 v1 = xs[1];
        const float4 v2 = xs[2];
        const float a[12] = { v0.x, v0.y, v0.z, v0.w,
                              v1.x, v1.y, v1.z, v1.w,
                              v2.x, v2.y, v2.z, v2.w };

        const float4 q0 = M4[q * 3 + 0];
        const float4 q1 = M4[q * 3 + 1];
        const float4 q2 = M4[q * 3 + 2];
        const float m[9] = { q0.x, q0.y, q0.z, q0.w,
                             q1.x, q1.y, q1.z, q1.w, q2.x };

        #pragma unroll
        for (int u = 0; u < 4; ++u)
            #pragma unroll
            for (int k = 0; k < 3; ++k)
                acc[u * 3 + k] += a[u * 3 + 0] * m[0 + k]
                                + a[u * 3 + 1] * m[3 + k]
                                + a[u * 3 + 2] * m[6 + k];

        const int oo = s_out[q];          // warp-uniform branch
        if (oo >= 0) {
            float4* o = (float4*)(outb + oo) + t3;
            o[0] = make_float4(acc[0], acc[1], acc[2],  acc[3]);
            o[1] = make_float4(acc[4], acc[5], acc[6],  acc[7]);
            o[2] = make_float4(acc[8], acc[9], acc[10], acc[11]);
            #pragma unroll
            for (int i = 0; i < 12; ++i) acc[i] = 0.f;
        }
    }

    // Zero-fill empty segments (poisoned output); split by segment parity.
    const float4 z = make_float4(0.f, 0.f, 0.f, 0.f);
    #pragma unroll
    for (int s = 0; s < NUM_SEG; ++s) {
        const int eo = s_empty[s];
        if (eo >= 0 && (s & 1) == half) {
            float4* o = (float4*)(outb + eo) + t3;
            o[0] = z; o[1] = z; o[2] = z;
        }
    }
}

extern "C" void kernel_launch(void* const* d_in, const int* in_sizes, int n_in,
                              void* d_out, int out_size)
{
    const float* x0    = (const float*)d_in[0];  // (2048, 12288)
    const float* x1    = (const float*)d_in[1];  // (2048, 96)
    const float* coeff = (const float*)d_in[2];  // (64, 27)
    const int*   idx0  = (const int*)d_in[3];
    const int*   idx1  = (const int*)d_in[4];
    const int*   idx2  = (const int*)d_in[5];
    float*       out   = (float*)d_out;          // (2048, 12288)

    const int batch = in_sizes[0] / ROW_ELEMS;   // 2048
    ftp3_main<<<batch / ROWS_PER_CTA, 128>>>(x0, x1, coeff, idx0, idx1, idx2, out);
}

// round 14
// speedup vs baseline: 1.2936x; 1.0846x over previous
#include <cuda_runtime.h>
#include <cstdlib>

#define NUM_SEG   32
#define MUL       128
#define D         3
#define NUM_PATHS 64
#define SEG_ELEMS (MUL * D)              // 384 floats per segment
#define ROW_ELEMS (NUM_SEG * SEG_ELEMS)  // 12288 floats per batch row

__global__ __launch_bounds__(128, 5)     // ~100 regs: full per-warp MLP
void ftp3_main(const float* __restrict__ x0,
               const float* __restrict__ x1,
               const float* __restrict__ coeff,
               const int*   __restrict__ idx0,
               const int*   __restrict__ idx1,
               const int*   __restrict__ idx2,
               float*       __restrict__ out)
{
    // One batch row per CTA; 4 warps split the sorted path list 4 ways.
    __shared__ __align__(16) float M[NUM_PATHS * 12];
    __shared__ int s_idx2[NUM_PATHS];
    __shared__ int s_key[NUM_PATHS];      // rank -> segment key (sorted)
    __shared__ int s_porder[NUM_PATHS];   // rank -> original path id
    __shared__ int s_off0[NUM_PATHS];     // rank -> idx0[p]*SEG_ELEMS
    __shared__ int s_out[NUM_PATHS];      // rank -> seg*SEG_ELEMS at boundary, else -1
    __shared__ int s_empty[NUM_SEG];      // seg offset to zero-fill, or -1
    __shared__ int s_best[3];             // packed splits near 16/32/48: (dist<<8)|r

    const int t    = threadIdx.x;
    const int w    = t >> 5;              // 0..3: which quarter of the path list
    const int lane = t & 31;
    const int b    = blockIdx.x;          // one batch row per CTA

    if (t < NUM_PATHS) s_idx2[t] = idx2[t];
    if (t >= NUM_PATHS && t < NUM_PATHS + 3) s_best[t - NUM_PATHS] = 0x7fffffff;
    __syncthreads();

    // Stage 1: stable counting-rank by idx2 (partial unroll: fast, small
    // live-set) + empty-segment scan on the spare threads.
    if (t < NUM_PATHS) {
        const int key = s_idx2[t];
        int r = 0, nlater = 0;
        #pragma unroll 4
        for (int q = 0; q < NUM_PATHS; ++q) {
            const int kq = s_idx2[q];
            r      += (kq < key) | ((kq == key) & (q < t));
            nlater += (kq == key) & (q > t);
        }
        s_key[r]    = key;
        s_porder[r] = t;
        s_off0[r]   = idx0[t] * SEG_ELEMS;
        s_out[r]    = (nlater == 0) ? key * SEG_ELEMS : -1;
    } else if (t < NUM_PATHS + NUM_SEG) {
        const int s = t - NUM_PATHS;
        int c = 0;
        #pragma unroll 4
        for (int q = 0; q < NUM_PATHS; ++q) c += (s_idx2[q] == s);
        s_empty[s] = (c == 0) ? s * SEG_ELEMS : -1;
    }
    __syncthreads();

    // Stage 2a: parallel search for segment-aligned splits near 16/32/48.
    if (t >= 1 && t <= NUM_PATHS) {
        const bool bnd = (t == NUM_PATHS) || (s_key[t] != s_key[t - 1]);
        if (bnd) {
            atomicMin(&s_best[0], (abs(t - 16) << 8) | t);
            atomicMin(&s_best[1], (abs(t - 32) << 8) | t);
            atomicMin(&s_best[2], (abs(t - 48) << 8) | t);
        }
    }
    // Stage 2b: build M — threads <64, one rank each.
    if (t < NUM_PATHS) {
        const int p = s_porder[t];
        const float* c   = coeff + p * 27;                       // [i][j][k]
        const float* x1b = x1 + (size_t)b * (NUM_SEG * D) + idx1[p] * D;
        const float j0 = x1b[0], j1 = x1b[1], j2 = x1b[2];
        float* Mr = &M[t * 12];
        #pragma unroll
        for (int i = 0; i < 3; ++i)
            #pragma unroll
            for (int k = 0; k < 3; ++k)
                Mr[i * 3 + k] =
                    j0 * c[i * 9 + 0 * 3 + k] +
                    j1 * c[i * 9 + 1 * 3 + k] +
                    j2 * c[i * 9 + 2 * 3 + k];
        Mr[9] = 0.f; Mr[10] = 0.f; Mr[11] = 0.f;
    }
    __syncthreads();

    // Chunk bounds for this warp (clamped monotone; empty chunks are fine).
    int b1 = s_best[0] & 0xff;
    int b2 = s_best[1] & 0xff;
    int b3 = s_best[2] & 0xff;
    if (b2 < b1) b2 = b1;
    if (b3 < b2) b3 = b2;
    const int bounds[5] = { 0, b1, b2, b3, NUM_PATHS };
    const int qs = bounds[w];
    const int qe = bounds[w + 1];

    // Main loop (R11 body): lane owns u = 4*lane..4*lane+3 -> 3 aligned
    // float4 per segment; every LDG/STG is a fully-coalesced 512B warp txn.
    const float*  x0b  = x0  + (size_t)b * ROW_ELEMS;
    float*        outb = out + (size_t)b * ROW_ELEMS;
    const float4* M4   = (const float4*)M;
    const int     t3   = lane * 3;

    float acc[12];
    #pragma unroll
    for (int i = 0; i < 12; ++i) acc[i] = 0.f;

    #pragma unroll 4
    for (int q = qs; q < qe; ++q) {
        const float4* xs = (const float4*)(x0b + s_off0[q]) + t3;
        const float4 v0 = xs[0];
        const float4 v1 = xs[1];
        const float4 v2 = xs[2];
        const float a[12] = { v0.x, v0.y, v0.z, v0.w,
                              v1.x, v1.y, v1.z, v1.w,
                              v2.x, v2.y, v2.z, v2.w };

        const float4 q0 = M4[q * 3 + 0];
        const float4 q1 = M4[q * 3 + 1];
        const float4 q2 = M4[q * 3 + 2];
        const float m[9] = { q0.x, q0.y, q0.z, q0.w,
                             q1.x, q1.y, q1.z, q1.w, q2.x };

        #pragma unroll
        for (int u = 0; u < 4; ++u)
            #pragma unroll
            for (int k = 0; k < 3; ++k)
                acc[u * 3 + k] += a[u * 3 + 0] * m[0 + k]
                                + a[u * 3 + 1] * m[3 + k]
                                + a[u * 3 + 2] * m[6 + k];

        const int oo = s_out[q];          // warp-uniform branch
        if (oo >= 0) {
            float4* o = (float4*)(outb + oo) + t3;
            o[0] = make_float4(acc[0], acc[1], acc[2],  acc[3]);
            o[1] = make_float4(acc[4], acc[5], acc[6],  acc[7]);
            o[2] = make_float4(acc[8], acc[9], acc[10], acc[11]);
            #pragma unroll
            for (int i = 0; i < 12; ++i) acc[i] = 0.f;
        }
    }

    // Zero-fill empty segments (poisoned output); spread across 4 warps.
    const float4 z = make_float4(0.f, 0.f, 0.f, 0.f);
    #pragma unroll
    for (int s = 0; s < NUM_SEG; ++s) {
        const int eo = s_empty[s];
        if (eo >= 0 && (s & 3) == w) {
            float4* o = (float4*)(outb + eo) + t3;
            o[0] = z; o[1] = z; o[2] = z;
        }
    }
}

extern "C" void kernel_launch(void* const* d_in, const int* in_sizes, int n_in,
                              void* d_out, int out_size)
{
    const float* x0    = (const float*)d_in[0];  // (2048, 12288)
    const float* x1    = (const float*)d_in[1];  // (2048, 96)
    const float* coeff = (const float*)d_in[2];  // (64, 27)
    const int*   idx0  = (const int*)d_in[3];
    const int*   idx1  = (const int*)d_in[4];
    const int*   idx2  = (const int*)d_in[5];
    float*       out   = (float*)d_out;          // (2048, 12288)

    const int batch = in_sizes[0] / ROW_ELEMS;   // 2048
    ftp3_main<<<batch, 128>>>(x0, x1, coeff, idx0, idx1, idx2, out);
}